// round 11
// baseline (speedup 1.0000x reference)
#include <cuda_runtime.h>
#include <math.h>

// Problem constants (fixed by the dataset instance)
#define BATCH   8
#define NP      4096
#define FDIM    512
#define H1DIM   256
#define H2DIM   128
#define DDIM    6

#define FSCORE_W 0.1f
#define TASK_W   1.0f
#define DOMAIN_W 0.1f
#define INV_C    5000.0f       // 1/(2*sigma^2)

// z-bucket grid. +-6 sigma: N(0,1) data never clamps, so bucket order is
// monotone in z up to one bucket width W of within-bucket disorder:
//   for positions i < j in bucket order:  z_i <= z_j + W.
#define NB      256
#define BMIN    (-6.0f)
#define BWID    (12.0f / NB)           // 0.046875
#define INV_BW  (NB / 12.0f)

#define LPAD    32
#define RPAD    32
#define NPP     (NP + LPAD + RPAD)     // 4160

#define QCHUNK  256                    // queries per chamfer block (8 warps)
#define NCHUNKS (NP / QCHUNK)          // 16
#define NARRIVE (NCHUNKS * 2 * BATCH + BATCH)   // 256 chamfer + 8 domain
#define DSMEM   (NPP * 16)             // dynamic smem: float4 keys

// Scratch (device globals; every slot written unconditionally each launch).
__device__ float4 g_b4[2][BATCH][NPP];   // bucket-ordered (x,y,z,0) + sentinels
__device__ int    g_start[2][BATCH][NB];
__device__ float  g_r3[2][BATCH][NCHUNKS][2];  // per-block (sum_d, sum_exp)
__device__ float  g_dom[BATCH];
__device__ int    g_ctr = 0;             // zero-init; self-resetting

// ============================ Launch 1 ============================
// One block per (cloud, batch): histogram z -> prefix -> scatter float4,
// write sentinels. O(N).
__global__ __launch_bounds__(256) void bucket_kernel(
    const float* __restrict__ P, const float* __restrict__ T)
{
    __shared__ int cnt[NB];
    __shared__ int inc[NB];
    __shared__ int tmp[NB];
    __shared__ int boff[NB];

    const int tid   = threadIdx.x;
    const int cloud = blockIdx.x & 1;
    const int b     = blockIdx.x >> 1;
    const float* src = cloud ? (T + (size_t)b * NP * 3)
                             : (P + (size_t)b * NP * 3);

    cnt[tid] = 0;
    __syncthreads();
    for (int i = tid; i < NP; i += 256) {
        float z = src[i * 3 + 2];
        int bk = min(max((int)((z - BMIN) * INV_BW), 0), NB - 1);
        atomicAdd(&cnt[bk], 1);
    }
    __syncthreads();
    inc[tid] = cnt[tid];
    __syncthreads();
    #pragma unroll
    for (int d = 1; d < NB; d <<= 1) {
        tmp[tid] = (tid >= d) ? inc[tid - d] + inc[tid] : inc[tid];
        __syncthreads();
        inc[tid] = tmp[tid];
        __syncthreads();
    }
    boff[tid] = inc[tid] - cnt[tid];   // exclusive prefix
    cnt[tid] = 0;                      // reuse as scatter cursor
    __syncthreads();

    for (int i = tid; i < NP; i += 256) {
        float x = src[i * 3 + 0];
        float y = src[i * 3 + 1];
        float z = src[i * 3 + 2];
        int bk = min(max((int)((z - BMIN) * INV_BW), 0), NB - 1);
        int pos = LPAD + boff[bk] + atomicAdd(&cnt[bk], 1);
        g_b4[cloud][b][pos] = make_float4(x, y, z, 0.0f);
    }
    g_start[cloud][b][tid] = LPAD + boff[tid];

    if (tid < LPAD)
        g_b4[cloud][b][tid] = make_float4(1e30f, 1e30f, -1e30f, 0.0f);
    if (tid < RPAD)
        g_b4[cloud][b][LPAD + NP + tid] = make_float4(1e30f, 1e30f, 1e30f, 0.0f);
}

// ---------------- domain MLP (rides in the chamfer launch) ----------------
__device__ __forceinline__ void domain_block(
    int b, int tid,
    const float* __restrict__ X,
    const float* __restrict__ W1, const float* __restrict__ b1,
    const float* __restrict__ W2, const float* __restrict__ b2,
    const float* __restrict__ W3, const float* __restrict__ b3,
    const int* __restrict__ labels)
{
    __shared__ float xs[FDIM];
    __shared__ float h1[H1DIM];
    __shared__ float h2[H2DIM];
    __shared__ float lg[DDIM];

    for (int i = tid; i < FDIM; i += QCHUNK) xs[i] = X[b * FDIM + i];
    __syncthreads();
    {   // layer 1: 256 threads x 1 output
        float a = b1[tid];
        #pragma unroll 8
        for (int f = 0; f < FDIM; f++)
            a = fmaf(xs[f], W1[f * H1DIM + tid], a);
        h1[tid] = fmaxf(a, 0.0f);
    }
    __syncthreads();
    if (tid < H2DIM) {   // layer 2
        float a = b2[tid];
        #pragma unroll 8
        for (int k = 0; k < H1DIM; k++)
            a = fmaf(h1[k], W2[k * H2DIM + tid], a);
        h2[tid] = fmaxf(a, 0.0f);
    }
    __syncthreads();
    if (tid < DDIM) {
        float a = b3[tid];
        #pragma unroll 8
        for (int k = 0; k < H2DIM; k++)
            a = fmaf(h2[k], W3[k * DDIM + tid], a);
        lg[tid] = a;
    }
    __syncthreads();
    if (tid == 0) {
        float mx = lg[0];
        for (int d = 1; d < DDIM; d++) mx = fmaxf(mx, lg[d]);
        float se = 0.f;
        for (int d = 0; d < DDIM; d++) se += expf(lg[d] - mx);
        g_dom[b] = (mx + logf(se)) - lg[labels[b]];
    }
    __syncthreads();
}

// Final combine (32 threads of whichever block arrives last).
__device__ __forceinline__ void final_combine(
    const float* __restrict__ dsw, float* __restrict__ out, int t)
{
    float sA = 0.f, sEA = 0.f, sB = 0.f, sEB = 0.f;
    float dwc = 0.f, domc = 0.f;
    if (t < BATCH) {
        #pragma unroll
        for (int c = 0; c < NCHUNKS; c++) {
            sA  += g_r3[0][t][c][0];
            sEA += g_r3[0][t][c][1];
            sB  += g_r3[1][t][c][0];
            sEB += g_r3[1][t][c][1];
        }
        const float invN = 1.0f / (float)NP;
        float ch_i = sA * invN + sB * invN;
        float p_i  = sEA * invN;
        float r_i  = sEB * invN;
        float f_i  = 2.0f * p_i * r_i / (p_i + r_i + 1e-8f);
        float loss_i = ch_i + FSCORE_W * (1.0f - f_i);
        dwc  = dsw[t] * loss_i;
        domc = g_dom[t];
    }
    #pragma unroll
    for (int s = 16; s > 0; s >>= 1) {
        sA   += __shfl_xor_sync(0xffffffffu, sA,   s);
        sEA  += __shfl_xor_sync(0xffffffffu, sEA,  s);
        sB   += __shfl_xor_sync(0xffffffffu, sB,   s);
        sEB  += __shfl_xor_sync(0xffffffffu, sEB,  s);
        dwc  += __shfl_xor_sync(0xffffffffu, dwc,  s);
        domc += __shfl_xor_sync(0xffffffffu, domc, s);
    }
    if (t == 0) {
        const float invBN = 1.0f / (float)(BATCH * NP);
        float chamfer = sA * invBN + sB * invBN;
        float prec = sEA * invBN;
        float rec  = sEB * invBN;
        float fscore = 2.0f * prec * rec / (prec + rec + 1e-8f);
        float task = chamfer + FSCORE_W * (1.0f - fscore);
        out[0] = TASK_W * task + DOMAIN_W * (domc / (float)BATCH)
               + (dwc / (float)BATCH);
    }
}

__device__ __forceinline__ void global_arrive(
    const float* __restrict__ dsw, float* __restrict__ out, int tid,
    int* sh_final)
{
    __threadfence();
    if (tid == 0) {
        int old = atomicAdd(&g_ctr, 1);
        *sh_final = (old == NARRIVE - 1) ? 1 : 0;
        if (*sh_final) atomicExch(&g_ctr, 0);   // reset for graph replay
    }
    __syncthreads();
    if (*sh_final && tid < 32) final_combine(dsw, out, tid);
}

// ============================ Launch 2 ============================
// Exact NN, warp-cooperative: the 32 lanes (32 consecutive bucket-ordered
// queries) walk the SAME key positions via broadcast LDS.128; each lane
// keeps its own best. Break tests are warp-uniform and exact:
//   right: all positions >= r have z >= z_r - W, so if
//          (z_r - W - qzmax)^2 >= max_lane(best) no lane can improve.
//   left : symmetric with qzmin. maxbest is refreshed every 32 keys;
//          between refreshes it is stale-high => conservative => exact.
__global__ __launch_bounds__(QCHUNK) void chamfer_kernel(
    const float* __restrict__ X,
    const float* __restrict__ W1, const float* __restrict__ b1,
    const float* __restrict__ W2, const float* __restrict__ b2,
    const float* __restrict__ W3, const float* __restrict__ b3,
    const int* __restrict__ labels,
    const float* __restrict__ dsw, float* __restrict__ out)
{
    __shared__ int sh_final;
    const int tid = threadIdx.x;
    const int b   = blockIdx.z;

    if (blockIdx.y == 2) {
        if (blockIdx.x == 0) {
            domain_block(b, tid, X, W1, b1, W2, b2, W3, b3, labels);
            global_arrive(dsw, out, tid, &sh_final);
        }
        return;
    }

    extern __shared__ float4 sk[];           // NPP float4 keys (66.5 KB)
    __shared__ unsigned short sStart[NB];
    __shared__ float red[8][2];

    const int chunk = blockIdx.x;
    const int dir   = blockIdx.y;   // queries = cloud dir, keys = cloud 1-dir
    const int kc    = 1 - dir;

    for (int i = tid; i < NPP; i += QCHUNK) sk[i] = g_b4[kc][b][i];
    if (tid < NB) sStart[tid] = (unsigned short)g_start[kc][b][tid];

    const int q = LPAD + chunk * QCHUNK + tid;
    const float4 qq = g_b4[dir][b][q];
    __syncthreads();

    // warp z-range of queries
    float qzmin = qq.z, qzmax = qq.z;
    #pragma unroll
    for (int s = 16; s > 0; s >>= 1) {
        qzmin = fminf(qzmin, __shfl_xor_sync(0xffffffffu, qzmin, s));
        qzmax = fmaxf(qzmax, __shfl_xor_sync(0xffffffffu, qzmax, s));
    }
    const int qb0 = min(max((int)((qzmin - BMIN) * INV_BW), 0), NB - 1);
    const int rs  = sStart[qb0];

    float best    = 1e30f;
    float maxbest = 1e30f;

    // right sweep: positions rs, rs+1, ... (covers all keys with z >= qzmin's
    // bucket bottom; remaining keys handled by the left sweep)
    int r = rs;
    while (true) {
        float s = sk[r].z - qzmax - BWID;
        if (s > 0.0f && s * s >= maxbest) break;
        #pragma unroll
        for (int g = 0; g < 4; g++) {
            float m = 1e30f;
            #pragma unroll
            for (int u = 0; u < 8; u++) {
                float4 kk = sk[r + g * 8 + u];   // broadcast LDS.128
                float dx = kk.x - qq.x;
                float dy = kk.y - qq.y;
                float dz = kk.z - qq.z;
                m = fminf(m, fmaf(dx, dx, fmaf(dy, dy, dz * dz)));
            }
            best = fminf(best, m);
        }
        r += 32;
        float mb = best;
        #pragma unroll
        for (int s2 = 16; s2 > 0; s2 >>= 1)
            mb = fmaxf(mb, __shfl_xor_sync(0xffffffffu, mb, s2));
        maxbest = mb;   // finite after first iteration
    }

    // left sweep: positions rs-1, rs-2, ...
    int l = rs - 1;
    while (true) {
        float t = qzmin - sk[l].z - BWID;
        if (t > 0.0f && t * t >= maxbest) break;
        #pragma unroll
        for (int g = 0; g < 4; g++) {
            float m = 1e30f;
            #pragma unroll
            for (int u = 0; u < 8; u++) {
                float4 kk = sk[l - g * 8 - u];   // broadcast LDS.128
                float dx = kk.x - qq.x;
                float dy = kk.y - qq.y;
                float dz = kk.z - qq.z;
                m = fminf(m, fmaf(dx, dx, fmaf(dy, dy, dz * dz)));
            }
            best = fminf(best, m);
        }
        l -= 32;
        float mb = best;
        #pragma unroll
        for (int s2 = 16; s2 > 0; s2 >>= 1)
            mb = fmaxf(mb, __shfl_xor_sync(0xffffffffu, mb, s2));
        maxbest = mb;
    }

    // block reduction of (sum_d, sum_exp)
    float sd = best;
    float se = __expf(-best * INV_C);
    #pragma unroll
    for (int s = 16; s > 0; s >>= 1) {
        sd += __shfl_xor_sync(0xffffffffu, sd, s);
        se += __shfl_xor_sync(0xffffffffu, se, s);
    }
    int w = tid >> 5;
    if ((tid & 31) == 0) { red[w][0] = sd; red[w][1] = se; }
    __syncthreads();
    if (tid == 0) {
        float a0 = 0.f, a1 = 0.f;
        #pragma unroll
        for (int ww = 0; ww < 8; ww++) { a0 += red[ww][0]; a1 += red[ww][1]; }
        g_r3[dir][b][chunk][0] = a0;
        g_r3[dir][b][chunk][1] = a1;
    }

    global_arrive(dsw, out, tid, &sh_final);
}

extern "C" void kernel_launch(void* const* d_in, const int* in_sizes, int n_in,
                              void* d_out, int out_size)
{
    const float* pred_pc   = (const float*)d_in[0];
    const float* target_pc = (const float*)d_in[1];
    const float* dfeat     = (const float*)d_in[2];
    const float* dsw       = (const float*)d_in[3];
    const float* W1 = (const float*)d_in[4];
    const float* b1 = (const float*)d_in[5];
    const float* W2 = (const float*)d_in[6];
    const float* b2 = (const float*)d_in[7];
    const float* W3 = (const float*)d_in[8];
    const float* b3 = (const float*)d_in[9];
    const int*   labels = (const int*)d_in[10];
    float* out = (float*)d_out;

    static int attr_done = 0;
    if (!attr_done) {
        cudaFuncSetAttribute(chamfer_kernel,
                             cudaFuncAttributeMaxDynamicSharedMemorySize,
                             DSMEM);
        attr_done = 1;
    }

    bucket_kernel<<<16, 256>>>(pred_pc, target_pc);

    // (16, 3, 8): y<2 chamfer dirs; y==2,x==0 domain blocks.
    dim3 grid(NCHUNKS, 3, BATCH);
    chamfer_kernel<<<grid, QCHUNK, DSMEM>>>(dfeat, W1, b1, W2, b2, W3, b3,
                                            labels, dsw, out);
}

// round 12
// speedup vs baseline: 1.1909x; 1.1909x over previous
#include <cuda_runtime.h>
#include <math.h>

// Problem constants (fixed by the dataset instance)
#define BATCH   8
#define NP      4096
#define FDIM    512
#define H1DIM   256
#define H2DIM   128
#define DDIM    6

#define FSCORE_W 0.1f
#define TASK_W   1.0f
#define DOMAIN_W 0.1f
#define INV_C    5000.0f       // 1/(2*sigma^2)

// z-bucket grid for ordering only (exactness never relies on bucket width).
#define NB      256
#define BMIN    (-6.0f)
#define INV_BW  (NB / 12.0f)

#define TPB     128
#define PPT     2
#define QPB     (TPB*PPT)      // 256 queries per chamfer block
#define NQB     (NP/QPB)       // 16
#define NTILE   32             // key tiles of 128
#define JPT     64             // packed key-pairs per tile
#define NARRIVE (NQB*2*BATCH + BATCH)   // 256 chamfer + 8 domain = 264

// Scratch (device globals; every slot written unconditionally each launch).
__device__ float4     g_q4[2][BATCH][NP];      // z-ordered (x,y,z,0)
__device__ ulonglong2 g_pA[2][BATCH][NP/2];    // {-2x pair},{-2y pair}
__device__ ulonglong2 g_pB[2][BATCH][NP/2];    // {-2z pair},{|k|^2 pair}
__device__ int        g_start[2][BATCH][NB];
__device__ float      g_sufmin[2][BATCH][NTILE];  // min z over tiles >= t
__device__ float      g_premax[2][BATCH][NTILE];  // max z over tiles <= t
__device__ float      g_r3[2][BATCH][NQB][2];  // per-block (sum_d, sum_exp)
__device__ float      g_dom[BATCH];
__device__ int        g_ctr = 0;               // zero-init; self-resetting

// ---------------- f32x2 helpers (sm_100+ packed fp32) ----------------
__device__ __forceinline__ unsigned long long pack2(float lo, float hi) {
    unsigned long long r;
    asm("mov.b64 %0, {%1, %2};" : "=l"(r) : "f"(lo), "f"(hi));
    return r;
}
__device__ __forceinline__ unsigned long long fma2(unsigned long long a,
                                                   unsigned long long b,
                                                   unsigned long long c) {
    unsigned long long r;
    asm("fma.rn.f32x2 %0, %1, %2, %3;" : "=l"(r) : "l"(a), "l"(b), "l"(c));
    return r;
}
__device__ __forceinline__ float2 unpack2(unsigned long long v) {
    float2 f;
    asm("mov.b64 {%0, %1}, %2;" : "=f"(f.x), "=f"(f.y) : "l"(v));
    return f;
}

// sortable-uint encoding of float (order-preserving)
__device__ __forceinline__ unsigned fenc(float f) {
    unsigned u = __float_as_uint(f);
    return (u & 0x80000000u) ? ~u : (u | 0x80000000u);
}
__device__ __forceinline__ float fdec(unsigned u) {
    unsigned v = (u & 0x80000000u) ? (u & 0x7fffffffu) : ~u;
    return __uint_as_float(v);
}

// ============================ Launch 1 ============================
// One block per (cloud, batch): histogram z -> prefix -> scatter into
// z-bucket order -> pack FFMA2 key pairs -> exact per-tile z stats ->
// suffix-min / prefix-max. O(N).
__global__ __launch_bounds__(256) void bucket_kernel(
    const float* __restrict__ P, const float* __restrict__ T)
{
    __shared__ int cnt[NB];
    __shared__ int inc[NB];
    __shared__ int tmp[NB];
    __shared__ int boff[NB];
    __shared__ unsigned tzmin[NTILE], tzmax[NTILE];

    const int tid   = threadIdx.x;
    const int cloud = blockIdx.x & 1;
    const int b     = blockIdx.x >> 1;
    const float* src = cloud ? (T + (size_t)b * NP * 3)
                             : (P + (size_t)b * NP * 3);

    cnt[tid] = 0;
    if (tid < NTILE) { tzmin[tid] = 0xFFFFFFFFu; tzmax[tid] = 0u; }
    __syncthreads();
    for (int i = tid; i < NP; i += 256) {
        float z = src[i * 3 + 2];
        int bk = min(max((int)((z - BMIN) * INV_BW), 0), NB - 1);
        atomicAdd(&cnt[bk], 1);
    }
    __syncthreads();
    inc[tid] = cnt[tid];
    __syncthreads();
    #pragma unroll
    for (int d = 1; d < NB; d <<= 1) {
        tmp[tid] = (tid >= d) ? inc[tid - d] + inc[tid] : inc[tid];
        __syncthreads();
        inc[tid] = tmp[tid];
        __syncthreads();
    }
    boff[tid] = inc[tid] - cnt[tid];   // exclusive prefix
    cnt[tid] = 0;                      // reuse as scatter cursor
    __syncthreads();

    for (int i = tid; i < NP; i += 256) {
        float x = src[i * 3 + 0];
        float y = src[i * 3 + 1];
        float z = src[i * 3 + 2];
        int bk = min(max((int)((z - BMIN) * INV_BW), 0), NB - 1);
        int pos = boff[bk] + atomicAdd(&cnt[bk], 1);
        g_q4[cloud][b][pos] = make_float4(x, y, z, 0.0f);
    }
    g_start[cloud][b][tid] = boff[tid];
    __syncthreads();   // g_q4 writes visible block-wide

    // pack pairs + exact per-tile z min/max
    for (int j = tid; j < NP / 2; j += 256) {
        float4 k0 = g_q4[cloud][b][2 * j];
        float4 k1 = g_q4[cloud][b][2 * j + 1];
        ulonglong2 A, B;
        A.x = pack2(-2.0f * k0.x, -2.0f * k1.x);
        A.y = pack2(-2.0f * k0.y, -2.0f * k1.y);
        B.x = pack2(-2.0f * k0.z, -2.0f * k1.z);
        B.y = pack2(k0.x * k0.x + k0.y * k0.y + k0.z * k0.z,
                    k1.x * k1.x + k1.y * k1.y + k1.z * k1.z);
        g_pA[cloud][b][j] = A;
        g_pB[cloud][b][j] = B;
        int t = j >> 6;   // tile index (64 pairs per tile)
        unsigned e0 = fenc(k0.z), e1 = fenc(k1.z);
        atomicMin(&tzmin[t], min(e0, e1));
        atomicMax(&tzmax[t], max(e0, e1));
    }
    __syncthreads();
    if (tid == 0) {
        float run = 1e30f;
        for (int t = NTILE - 1; t >= 0; t--) {
            run = fminf(run, fdec(tzmin[t]));
            g_sufmin[cloud][b][t] = run;
        }
        run = -1e30f;
        for (int t = 0; t < NTILE; t++) {
            run = fmaxf(run, fdec(tzmax[t]));
            g_premax[cloud][b][t] = run;
        }
    }
}

// ---------------- domain MLP (rides in the chamfer launch) ----------------
__device__ __forceinline__ void domain_block(
    int b, int tid,
    const float* __restrict__ X,
    const float* __restrict__ W1, const float* __restrict__ b1,
    const float* __restrict__ W2, const float* __restrict__ b2,
    const float* __restrict__ W3, const float* __restrict__ b3,
    const int* __restrict__ labels)
{
    __shared__ float xs[FDIM];
    __shared__ float h1[H1DIM];
    __shared__ float h2[H2DIM];
    __shared__ float lg[DDIM];

    for (int i = tid; i < FDIM; i += TPB) xs[i] = X[b * FDIM + i];
    __syncthreads();
    {   // layer 1: 128 threads x 2 outputs
        float a0 = b1[tid], a1 = b1[tid + 128];
        #pragma unroll 8
        for (int f = 0; f < FDIM; f++) {
            float x = xs[f];
            a0 = fmaf(x, W1[f * H1DIM + tid],       a0);
            a1 = fmaf(x, W1[f * H1DIM + tid + 128], a1);
        }
        h1[tid]       = fmaxf(a0, 0.0f);
        h1[tid + 128] = fmaxf(a1, 0.0f);
    }
    __syncthreads();
    {   // layer 2
        float a = b2[tid];
        #pragma unroll 8
        for (int k = 0; k < H1DIM; k++)
            a = fmaf(h1[k], W2[k * H2DIM + tid], a);
        h2[tid] = fmaxf(a, 0.0f);
    }
    __syncthreads();
    if (tid < DDIM) {
        float a = b3[tid];
        #pragma unroll 8
        for (int k = 0; k < H2DIM; k++)
            a = fmaf(h2[k], W3[k * DDIM + tid], a);
        lg[tid] = a;
    }
    __syncthreads();
    if (tid == 0) {
        float mx = lg[0];
        for (int d = 1; d < DDIM; d++) mx = fmaxf(mx, lg[d]);
        float se = 0.f;
        for (int d = 0; d < DDIM; d++) se += expf(lg[d] - mx);
        g_dom[b] = (mx + logf(se)) - lg[labels[b]];
    }
    __syncthreads();
}

// Final combine (32 threads of whichever block arrives last).
__device__ __forceinline__ void final_combine(
    const float* __restrict__ dsw, float* __restrict__ out, int t)
{
    float sA = 0.f, sEA = 0.f, sB = 0.f, sEB = 0.f;
    float dwc = 0.f, domc = 0.f;
    if (t < BATCH) {
        #pragma unroll
        for (int c = 0; c < NQB; c++) {
            sA  += g_r3[0][t][c][0];
            sEA += g_r3[0][t][c][1];
            sB  += g_r3[1][t][c][0];
            sEB += g_r3[1][t][c][1];
        }
        const float invN = 1.0f / (float)NP;
        float ch_i = sA * invN + sB * invN;
        float p_i  = sEA * invN;
        float r_i  = sEB * invN;
        float f_i  = 2.0f * p_i * r_i / (p_i + r_i + 1e-8f);
        float loss_i = ch_i + FSCORE_W * (1.0f - f_i);
        dwc  = dsw[t] * loss_i;
        domc = g_dom[t];
    }
    #pragma unroll
    for (int s = 16; s > 0; s >>= 1) {
        sA   += __shfl_xor_sync(0xffffffffu, sA,   s);
        sEA  += __shfl_xor_sync(0xffffffffu, sEA,  s);
        sB   += __shfl_xor_sync(0xffffffffu, sB,   s);
        sEB  += __shfl_xor_sync(0xffffffffu, sEB,  s);
        dwc  += __shfl_xor_sync(0xffffffffu, dwc,  s);
        domc += __shfl_xor_sync(0xffffffffu, domc, s);
    }
    if (t == 0) {
        const float invBN = 1.0f / (float)(BATCH * NP);
        float chamfer = sA * invBN + sB * invBN;
        float prec = sEA * invBN;
        float rec  = sEB * invBN;
        float fscore = 2.0f * prec * rec / (prec + rec + 1e-8f);
        float task = chamfer + FSCORE_W * (1.0f - fscore);
        out[0] = TASK_W * task + DOMAIN_W * (domc / (float)BATCH)
               + (dwc / (float)BATCH);
    }
}

__device__ __forceinline__ void global_arrive(
    const float* __restrict__ dsw, float* __restrict__ out, int tid,
    int* sh_final)
{
    __threadfence();
    if (tid == 0) {
        int old = atomicAdd(&g_ctr, 1);
        *sh_final = (old == NARRIVE - 1) ? 1 : 0;
        if (*sh_final) atomicExch(&g_ctr, 0);   // reset for graph replay
    }
    __syncthreads();
    if (*sh_final && tid < 32) final_combine(dsw, out, tid);
}

// ============================ Launch 2 ============================
// Windowed brute force: the proven packed-FFMA2 loop over whole 128-key
// tiles, scanned outward in z order with a BLOCK-UNIFORM exact break:
//   skip right tiles >= t when (sufmin[t] - qzmax)^2 >= bb, where bb =
//   max over the block's queries of their CURRENT best (stale-high =>
//   conservative => exact); left side symmetric with premax/qzmin.
__global__ __launch_bounds__(TPB) void chamfer_kernel(
    const float* __restrict__ X,
    const float* __restrict__ W1, const float* __restrict__ b1,
    const float* __restrict__ W2, const float* __restrict__ b2,
    const float* __restrict__ W3, const float* __restrict__ b3,
    const int* __restrict__ labels,
    const float* __restrict__ dsw, float* __restrict__ out)
{
    __shared__ int sh_final;
    const int tid = threadIdx.x;
    const int b   = blockIdx.z;

    if (blockIdx.y == 2) {
        if (blockIdx.x == 0) {
            domain_block(b, tid, X, W1, b1, W2, b2, W3, b3, labels);
            global_arrive(dsw, out, tid, &sh_final);
        }
        return;
    }

    __shared__ ulonglong2 sA[JPT], sB[JPT];
    __shared__ float ssuf[NTILE], spre[NTILE];
    __shared__ float rmm[4][2];
    __shared__ float bbw[4];
    __shared__ float red[4][2];
    __shared__ int   sh_t0;

    const int qb  = blockIdx.x;
    const int dir = blockIdx.y;
    const int kc  = 1 - dir;
    const int lane = tid & 31;
    const int w    = tid >> 5;

    // load queries (z-ordered cloud dir), pack
    unsigned long long qxd[PPT], qyd[PPT], qzd[PPT];
    float q2[PPT], emin[PPT];
    float zmn = 1e30f, zmx = -1e30f;
    #pragma unroll
    for (int p = 0; p < PPT; p++) {
        int pos = qb * QPB + p * TPB + tid;
        float4 qq = g_q4[dir][b][pos];
        qxd[p] = pack2(qq.x, qq.x);
        qyd[p] = pack2(qq.y, qq.y);
        qzd[p] = pack2(qq.z, qq.z);
        q2[p]  = qq.x * qq.x + qq.y * qq.y + qq.z * qq.z;
        emin[p] = 1e30f;
        zmn = fminf(zmn, qq.z);
        zmx = fmaxf(zmx, qq.z);
    }
    if (tid < NTILE) {
        ssuf[tid] = g_sufmin[kc][b][tid];
        spre[tid] = g_premax[kc][b][tid];
    }
    #pragma unroll
    for (int s = 16; s > 0; s >>= 1) {
        zmn = fminf(zmn, __shfl_xor_sync(0xffffffffu, zmn, s));
        zmx = fmaxf(zmx, __shfl_xor_sync(0xffffffffu, zmx, s));
    }
    if (lane == 0) { rmm[w][0] = zmn; rmm[w][1] = zmx; }
    __syncthreads();
    const float qzmin = fminf(fminf(rmm[0][0], rmm[1][0]),
                              fminf(rmm[2][0], rmm[3][0]));
    const float qzmax = fmaxf(fmaxf(rmm[0][1], rmm[1][1]),
                              fmaxf(rmm[2][1], rmm[3][1]));
    if (tid == 0) {
        int bk = min(max((int)((qzmin - BMIN) * INV_BW), 0), NB - 1);
        sh_t0 = min(g_start[kc][b][bk] >> 7, NTILE - 1);
    }
    __syncthreads();
    const int t0 = sh_t0;

    float bb = 1e30f;   // block max of current bests (uniform across threads)

    // ---- right sweep: tiles t0, t0+1, ... ----
    for (int t = t0; t < NTILE; t++) {
        float s = ssuf[t] - qzmax;
        if (s > 0.0f && s * s >= bb) break;
        if (tid < JPT) sA[tid] = g_pA[kc][b][t * JPT + tid];
        else           sB[tid - JPT] = g_pB[kc][b][t * JPT + tid - JPT];
        __syncthreads();
        #pragma unroll 8
        for (int j = 0; j < JPT; j++) {
            ulonglong2 A = sA[j];   // LDS.128 warp-uniform broadcast
            ulonglong2 B = sB[j];
            #pragma unroll
            for (int p = 0; p < PPT; p++) {
                unsigned long long e = fma2(qxd[p], A.x, B.y);
                e = fma2(qyd[p], A.y, e);
                e = fma2(qzd[p], B.x, e);
                float2 ef = unpack2(e);
                emin[p] = fminf(emin[p], fminf(ef.x, ef.y));
            }
        }
        float bd = fmaxf(emin[0] + q2[0], emin[1] + q2[1]);
        #pragma unroll
        for (int s2 = 16; s2 > 0; s2 >>= 1)
            bd = fmaxf(bd, __shfl_xor_sync(0xffffffffu, bd, s2));
        if (lane == 0) bbw[w] = bd;
        __syncthreads();
        bb = fmaxf(fmaxf(bbw[0], bbw[1]), fmaxf(bbw[2], bbw[3]));
    }

    // ---- left sweep: tiles t0-1, t0-2, ... ----
    for (int t = t0 - 1; t >= 0; t--) {
        float s = qzmin - spre[t];
        if (s > 0.0f && s * s >= bb) break;
        if (tid < JPT) sA[tid] = g_pA[kc][b][t * JPT + tid];
        else           sB[tid - JPT] = g_pB[kc][b][t * JPT + tid - JPT];
        __syncthreads();
        #pragma unroll 8
        for (int j = 0; j < JPT; j++) {
            ulonglong2 A = sA[j];
            ulonglong2 B = sB[j];
            #pragma unroll
            for (int p = 0; p < PPT; p++) {
                unsigned long long e = fma2(qxd[p], A.x, B.y);
                e = fma2(qyd[p], A.y, e);
                e = fma2(qzd[p], B.x, e);
                float2 ef = unpack2(e);
                emin[p] = fminf(emin[p], fminf(ef.x, ef.y));
            }
        }
        float bd = fmaxf(emin[0] + q2[0], emin[1] + q2[1]);
        #pragma unroll
        for (int s2 = 16; s2 > 0; s2 >>= 1)
            bd = fmaxf(bd, __shfl_xor_sync(0xffffffffu, bd, s2));
        if (lane == 0) bbw[w] = bd;
        __syncthreads();
        bb = fmaxf(fmaxf(bbw[0], bbw[1]), fmaxf(bbw[2], bbw[3]));
    }

    // ---- block reduction of (sum_d, sum_exp) ----
    float d0 = emin[0] + q2[0];
    float d1 = emin[1] + q2[1];
    float sd = d0 + d1;
    float se = __expf(-d0 * INV_C) + __expf(-d1 * INV_C);
    #pragma unroll
    for (int s = 16; s > 0; s >>= 1) {
        sd += __shfl_xor_sync(0xffffffffu, sd, s);
        se += __shfl_xor_sync(0xffffffffu, se, s);
    }
    if (lane == 0) { red[w][0] = sd; red[w][1] = se; }
    __syncthreads();
    if (tid == 0) {
        g_r3[dir][b][qb][0] = red[0][0] + red[1][0] + red[2][0] + red[3][0];
        g_r3[dir][b][qb][1] = red[0][1] + red[1][1] + red[2][1] + red[3][1];
    }

    global_arrive(dsw, out, tid, &sh_final);
}

extern "C" void kernel_launch(void* const* d_in, const int* in_sizes, int n_in,
                              void* d_out, int out_size)
{
    const float* pred_pc   = (const float*)d_in[0];
    const float* target_pc = (const float*)d_in[1];
    const float* dfeat     = (const float*)d_in[2];
    const float* dsw       = (const float*)d_in[3];
    const float* W1 = (const float*)d_in[4];
    const float* b1 = (const float*)d_in[5];
    const float* W2 = (const float*)d_in[6];
    const float* b2 = (const float*)d_in[7];
    const float* W3 = (const float*)d_in[8];
    const float* b3 = (const float*)d_in[9];
    const int*   labels = (const int*)d_in[10];
    float* out = (float*)d_out;

    bucket_kernel<<<16, 256>>>(pred_pc, target_pc);

    // (16, 3, 8): y<2 chamfer dirs; y==2,x==0 domain blocks.
    dim3 grid(NQB, 3, BATCH);
    chamfer_kernel<<<grid, TPB>>>(dfeat, W1, b1, W2, b2, W3, b3,
                                  labels, dsw, out);
}

// round 13
// speedup vs baseline: 1.5923x; 1.3371x over previous
#include <cuda_runtime.h>
#include <math.h>

// Problem constants (fixed by the dataset instance)
#define BATCH   8
#define NP      4096
#define FDIM    512
#define H1DIM   256
#define H2DIM   128
#define DDIM    6

#define FSCORE_W 0.1f
#define TASK_W   1.0f
#define DOMAIN_W 0.1f
#define INV_C    5000.0f       // 1/(2*sigma^2)

// z-bucket grid for ordering only (exactness never relies on bucket width).
#define NB      256
#define BMIN    (-6.0f)
#define INV_BW  (NB / 12.0f)

#define TPB     128
#define PPT     2
#define QPB     (TPB*PPT)      // 256 queries per chamfer group
#define NQB     (NP/QPB)       // 16
#define NTILE   32             // key tiles of 128
#define JPT     64             // packed key-pairs per tile
#define NSPLIT  2              // co-blocks per group (tile-interleaved)
#define NARRIVE (NQB*2*BATCH + BATCH)   // 256 group-finishers + 8 domain

// Scratch (device globals; every slot written unconditionally each launch).
__device__ float4     g_q4[2][BATCH][NP];      // z-ordered (x,y,z,0)
__device__ ulonglong2 g_pA[2][BATCH][NP/2];    // {-2x pair},{-2y pair}
__device__ ulonglong2 g_pB[2][BATCH][NP/2];    // {-2z pair},{|k|^2 pair}
__device__ int        g_start[2][BATCH][NB];
__device__ float      g_sufmin[2][BATCH][NTILE];  // min z over tiles >= t
__device__ float      g_premax[2][BATCH][NTILE];  // max z over tiles <= t
__device__ float      g_pm[2][BATCH][NQB][NSPLIT][QPB];  // per-split mins
__device__ float      g_r3[2][BATCH][NQB][2];  // per-group (sum_d, sum_exp)
__device__ float      g_dom[BATCH];
__device__ int        g_ctr_g[2][BATCH][NQB];  // group counters (self-reset)
__device__ int        g_ctr = 0;               // global counter (self-reset)

// ---------------- f32x2 helpers (sm_100+ packed fp32) ----------------
__device__ __forceinline__ unsigned long long pack2(float lo, float hi) {
    unsigned long long r;
    asm("mov.b64 %0, {%1, %2};" : "=l"(r) : "f"(lo), "f"(hi));
    return r;
}
__device__ __forceinline__ unsigned long long fma2(unsigned long long a,
                                                   unsigned long long b,
                                                   unsigned long long c) {
    unsigned long long r;
    asm("fma.rn.f32x2 %0, %1, %2, %3;" : "=l"(r) : "l"(a), "l"(b), "l"(c));
    return r;
}
__device__ __forceinline__ float2 unpack2(unsigned long long v) {
    float2 f;
    asm("mov.b64 {%0, %1}, %2;" : "=f"(f.x), "=f"(f.y) : "l"(v));
    return f;
}
__device__ __forceinline__ unsigned fenc(float f) {
    unsigned u = __float_as_uint(f);
    return (u & 0x80000000u) ? ~u : (u | 0x80000000u);
}
__device__ __forceinline__ float fdec(unsigned u) {
    unsigned v = (u & 0x80000000u) ? (u & 0x7fffffffu) : ~u;
    return __uint_as_float(v);
}

// ============================ Launch 1 ============================
// One 512-thread block per (cloud, batch): histogram z -> prefix -> scatter
// into z-bucket order -> pack FFMA2 key pairs -> exact per-tile z stats.
__global__ __launch_bounds__(512) void bucket_kernel(
    const float* __restrict__ P, const float* __restrict__ T)
{
    __shared__ int cnt[NB];
    __shared__ int inc[NB];
    __shared__ int tmp[NB];
    __shared__ int boff[NB];
    __shared__ unsigned tzmin[NTILE], tzmax[NTILE];

    const int tid   = threadIdx.x;
    const int cloud = blockIdx.x & 1;
    const int b     = blockIdx.x >> 1;
    const float* src = cloud ? (T + (size_t)b * NP * 3)
                             : (P + (size_t)b * NP * 3);

    if (tid < NB) cnt[tid] = 0;
    if (tid < NTILE) { tzmin[tid] = 0xFFFFFFFFu; tzmax[tid] = 0u; }
    __syncthreads();
    for (int i = tid; i < NP; i += 512) {
        float z = src[i * 3 + 2];
        int bk = min(max((int)((z - BMIN) * INV_BW), 0), NB - 1);
        atomicAdd(&cnt[bk], 1);
    }
    __syncthreads();
    if (tid < NB) inc[tid] = cnt[tid];
    __syncthreads();
    #pragma unroll
    for (int d = 1; d < NB; d <<= 1) {
        if (tid < NB) tmp[tid] = (tid >= d) ? inc[tid - d] + inc[tid] : inc[tid];
        __syncthreads();
        if (tid < NB) inc[tid] = tmp[tid];
        __syncthreads();
    }
    if (tid < NB) {
        boff[tid] = inc[tid] - cnt[tid];   // exclusive prefix
        cnt[tid] = 0;                      // reuse as scatter cursor
    }
    __syncthreads();

    for (int i = tid; i < NP; i += 512) {
        float x = src[i * 3 + 0];
        float y = src[i * 3 + 1];
        float z = src[i * 3 + 2];
        int bk = min(max((int)((z - BMIN) * INV_BW), 0), NB - 1);
        int pos = boff[bk] + atomicAdd(&cnt[bk], 1);
        g_q4[cloud][b][pos] = make_float4(x, y, z, 0.0f);
    }
    if (tid < NB) g_start[cloud][b][tid] = boff[tid];
    __syncthreads();   // g_q4 writes visible block-wide

    for (int j = tid; j < NP / 2; j += 512) {
        float4 k0 = g_q4[cloud][b][2 * j];
        float4 k1 = g_q4[cloud][b][2 * j + 1];
        ulonglong2 A, B;
        A.x = pack2(-2.0f * k0.x, -2.0f * k1.x);
        A.y = pack2(-2.0f * k0.y, -2.0f * k1.y);
        B.x = pack2(-2.0f * k0.z, -2.0f * k1.z);
        B.y = pack2(k0.x * k0.x + k0.y * k0.y + k0.z * k0.z,
                    k1.x * k1.x + k1.y * k1.y + k1.z * k1.z);
        g_pA[cloud][b][j] = A;
        g_pB[cloud][b][j] = B;
        int t = j >> 6;
        unsigned e0 = fenc(k0.z), e1 = fenc(k1.z);
        atomicMin(&tzmin[t], min(e0, e1));
        atomicMax(&tzmax[t], max(e0, e1));
    }
    __syncthreads();
    if (tid == 0) {
        float run = 1e30f;
        for (int t = NTILE - 1; t >= 0; t--) {
            run = fminf(run, fdec(tzmin[t]));
            g_sufmin[cloud][b][t] = run;
        }
    }
    if (tid == 1) {
        float run = -1e30f;
        for (int t = 0; t < NTILE; t++) {
            run = fmaxf(run, fdec(tzmax[t]));
            g_premax[cloud][b][t] = run;
        }
    }
}

// ---------------- domain MLP (rides in the chamfer launch) ----------------
__device__ __forceinline__ void domain_block(
    int b, int tid,
    const float* __restrict__ X,
    const float* __restrict__ W1, const float* __restrict__ b1,
    const float* __restrict__ W2, const float* __restrict__ b2,
    const float* __restrict__ W3, const float* __restrict__ b3,
    const int* __restrict__ labels)
{
    __shared__ float xs[FDIM];
    __shared__ float h1[H1DIM];
    __shared__ float h2[H2DIM];
    __shared__ float lg[DDIM];

    for (int i = tid; i < FDIM; i += TPB) xs[i] = X[b * FDIM + i];
    __syncthreads();
    {
        float a0 = b1[tid], a1 = b1[tid + 128];
        #pragma unroll 8
        for (int f = 0; f < FDIM; f++) {
            float x = xs[f];
            a0 = fmaf(x, W1[f * H1DIM + tid],       a0);
            a1 = fmaf(x, W1[f * H1DIM + tid + 128], a1);
        }
        h1[tid]       = fmaxf(a0, 0.0f);
        h1[tid + 128] = fmaxf(a1, 0.0f);
    }
    __syncthreads();
    {
        float a = b2[tid];
        #pragma unroll 8
        for (int k = 0; k < H1DIM; k++)
            a = fmaf(h1[k], W2[k * H2DIM + tid], a);
        h2[tid] = fmaxf(a, 0.0f);
    }
    __syncthreads();
    if (tid < DDIM) {
        float a = b3[tid];
        #pragma unroll 8
        for (int k = 0; k < H2DIM; k++)
            a = fmaf(h2[k], W3[k * DDIM + tid], a);
        lg[tid] = a;
    }
    __syncthreads();
    if (tid == 0) {
        float mx = lg[0];
        for (int d = 1; d < DDIM; d++) mx = fmaxf(mx, lg[d]);
        float se = 0.f;
        for (int d = 0; d < DDIM; d++) se += expf(lg[d] - mx);
        g_dom[b] = (mx + logf(se)) - lg[labels[b]];
    }
    __syncthreads();
}

// Final combine (32 threads of whichever block arrives last).
__device__ __forceinline__ void final_combine(
    const float* __restrict__ dsw, float* __restrict__ out, int t)
{
    float sA = 0.f, sEA = 0.f, sB = 0.f, sEB = 0.f;
    float dwc = 0.f, domc = 0.f;
    if (t < BATCH) {
        #pragma unroll
        for (int c = 0; c < NQB; c++) {
            sA  += g_r3[0][t][c][0];
            sEA += g_r3[0][t][c][1];
            sB  += g_r3[1][t][c][0];
            sEB += g_r3[1][t][c][1];
        }
        const float invN = 1.0f / (float)NP;
        float ch_i = sA * invN + sB * invN;
        float p_i  = sEA * invN;
        float r_i  = sEB * invN;
        float f_i  = 2.0f * p_i * r_i / (p_i + r_i + 1e-8f);
        float loss_i = ch_i + FSCORE_W * (1.0f - f_i);
        dwc  = dsw[t] * loss_i;
        domc = g_dom[t];
    }
    #pragma unroll
    for (int s = 16; s > 0; s >>= 1) {
        sA   += __shfl_xor_sync(0xffffffffu, sA,   s);
        sEA  += __shfl_xor_sync(0xffffffffu, sEA,  s);
        sB   += __shfl_xor_sync(0xffffffffu, sB,   s);
        sEB  += __shfl_xor_sync(0xffffffffu, sEB,  s);
        dwc  += __shfl_xor_sync(0xffffffffu, dwc,  s);
        domc += __shfl_xor_sync(0xffffffffu, domc, s);
    }
    if (t == 0) {
        const float invBN = 1.0f / (float)(BATCH * NP);
        float chamfer = sA * invBN + sB * invBN;
        float prec = sEA * invBN;
        float rec  = sEB * invBN;
        float fscore = 2.0f * prec * rec / (prec + rec + 1e-8f);
        float task = chamfer + FSCORE_W * (1.0f - fscore);
        out[0] = TASK_W * task + DOMAIN_W * (domc / (float)BATCH)
               + (dwc / (float)BATCH);
    }
}

__device__ __forceinline__ void global_arrive(
    const float* __restrict__ dsw, float* __restrict__ out, int tid,
    int* sh_final)
{
    __threadfence();
    if (tid == 0) {
        int old = atomicAdd(&g_ctr, 1);
        *sh_final = (old == NARRIVE - 1) ? 1 : 0;
        if (*sh_final) atomicExch(&g_ctr, 0);   // reset for graph replay
    }
    __syncthreads();
    if (*sh_final && tid < 32) final_combine(dsw, out, tid);
}

// ============================ Launch 2 ============================
// Windowed brute force, 2-way tile-interleaved co-blocks, double-buffered.
// Co-block `split` scans tiles t0+split, t0+split+2, ... rightward and
// t0-1-split, t0-3-split, ... leftward. Exact block-uniform breaks:
//   right: skip once (sufmin[next] - qzmax)^2 >= bb  (all keys in tiles
//          >= next have z >= sufmin[next]; bb = block-max of CURRENT
//          partial bests over this split's scanned keys >= true best).
//   left : symmetric with premax/qzmin.
__global__ __launch_bounds__(TPB) void chamfer_kernel(
    const float* __restrict__ X,
    const float* __restrict__ W1, const float* __restrict__ b1,
    const float* __restrict__ W2, const float* __restrict__ b2,
    const float* __restrict__ W3, const float* __restrict__ b3,
    const int* __restrict__ labels,
    const float* __restrict__ dsw, float* __restrict__ out)
{
    __shared__ int sh_final;
    const int tid = threadIdx.x;
    const int b   = blockIdx.z;

    if (blockIdx.y == 2 * NSPLIT) {
        if (blockIdx.x == 0) {
            domain_block(b, tid, X, W1, b1, W2, b2, W3, b3, labels);
            global_arrive(dsw, out, tid, &sh_final);
        }
        return;
    }

    __shared__ ulonglong2 sAb[2][JPT], sBb[2][JPT];   // double-buffered tiles
    __shared__ float ssuf[NTILE], spre[NTILE];
    __shared__ float rmm[4][2];
    __shared__ float bbw[4];
    __shared__ float red[4][2];
    __shared__ int   sh_t0, sh_last;

    const int qb    = blockIdx.x;
    const int dir   = blockIdx.y & 1;
    const int split = blockIdx.y >> 1;
    const int kc    = 1 - dir;
    const int lane  = tid & 31;
    const int w     = tid >> 5;

    // load + pack queries; block z-range
    unsigned long long qxd[PPT], qyd[PPT], qzd[PPT];
    float q2[PPT], emin[PPT];
    float zmn = 1e30f, zmx = -1e30f;
    #pragma unroll
    for (int p = 0; p < PPT; p++) {
        int pos = qb * QPB + p * TPB + tid;
        float4 qq = g_q4[dir][b][pos];
        qxd[p] = pack2(qq.x, qq.x);
        qyd[p] = pack2(qq.y, qq.y);
        qzd[p] = pack2(qq.z, qq.z);
        q2[p]  = qq.x * qq.x + qq.y * qq.y + qq.z * qq.z;
        emin[p] = 1e30f;
        zmn = fminf(zmn, qq.z);
        zmx = fmaxf(zmx, qq.z);
    }
    if (tid < NTILE) {
        ssuf[tid] = g_sufmin[kc][b][tid];
        spre[tid] = g_premax[kc][b][tid];
    }
    #pragma unroll
    for (int s = 16; s > 0; s >>= 1) {
        zmn = fminf(zmn, __shfl_xor_sync(0xffffffffu, zmn, s));
        zmx = fmaxf(zmx, __shfl_xor_sync(0xffffffffu, zmx, s));
    }
    if (lane == 0) { rmm[w][0] = zmn; rmm[w][1] = zmx; }
    __syncthreads();
    const float qzmin = fminf(fminf(rmm[0][0], rmm[1][0]),
                              fminf(rmm[2][0], rmm[3][0]));
    const float qzmax = fmaxf(fmaxf(rmm[0][1], rmm[1][1]),
                              fmaxf(rmm[2][1], rmm[3][1]));
    if (tid == 0) {
        int bk = min(max((int)((qzmin - BMIN) * INV_BW), 0), NB - 1);
        sh_t0 = min(g_start[kc][b][bk] >> 7, NTILE - 1);
    }
    __syncthreads();
    const int t0 = sh_t0;

    float bb = 1e30f;

    // ================= right sweep: t0+split, +2, ... =================
    {
        int cur = t0 + split;
        if (cur < NTILE) {
            // prologue: load tile cur into buffer 0
            if (tid < JPT) sAb[0][tid] = g_pA[kc][b][cur * JPT + tid];
            else           sBb[0][tid - JPT] = g_pB[kc][b][cur * JPT + tid - JPT];
            __syncthreads();
            int buf = 0;
            while (true) {
                int next = cur + NSPLIT;
                ulonglong2 pre;
                if (next < NTILE)
                    pre = (tid < JPT) ? g_pA[kc][b][next * JPT + tid]
                                      : g_pB[kc][b][next * JPT + tid - JPT];

                #pragma unroll 8
                for (int j = 0; j < JPT; j++) {
                    ulonglong2 A = sAb[buf][j];   // LDS.128 broadcast
                    ulonglong2 B = sBb[buf][j];
                    #pragma unroll
                    for (int p = 0; p < PPT; p++) {
                        unsigned long long e = fma2(qxd[p], A.x, B.y);
                        e = fma2(qyd[p], A.y, e);
                        e = fma2(qzd[p], B.x, e);
                        float2 ef = unpack2(e);
                        emin[p] = fminf(emin[p], fminf(ef.x, ef.y));
                    }
                }
                float bd = fmaxf(emin[0] + q2[0], emin[1] + q2[1]);
                #pragma unroll
                for (int s2 = 16; s2 > 0; s2 >>= 1)
                    bd = fmaxf(bd, __shfl_xor_sync(0xffffffffu, bd, s2));
                if (lane == 0) bbw[w] = bd;
                if (next < NTILE) {
                    if (tid < JPT) sAb[buf ^ 1][tid] = pre;
                    else           sBb[buf ^ 1][tid - JPT] = pre;
                }
                __syncthreads();
                bb = fmaxf(fmaxf(bbw[0], bbw[1]), fmaxf(bbw[2], bbw[3]));
                if (next >= NTILE) break;
                float sgap = ssuf[next] - qzmax;
                if (sgap > 0.0f && sgap * sgap >= bb) break;
                cur = next;
                buf ^= 1;
            }
        }
    }
    __syncthreads();   // buffers reused by left sweep

    // ================= left sweep: t0-1-split, -2, ... =================
    {
        int cur = t0 - 1 - split;
        if (cur >= 0) {
            // first-tile break check (bb may already be tight)
            float sgap0 = qzmin - spre[cur];
            if (!(sgap0 > 0.0f && sgap0 * sgap0 >= bb)) {
                if (tid < JPT) sAb[0][tid] = g_pA[kc][b][cur * JPT + tid];
                else           sBb[0][tid - JPT] = g_pB[kc][b][cur * JPT + tid - JPT];
                __syncthreads();
                int buf = 0;
                while (true) {
                    int next = cur - NSPLIT;
                    ulonglong2 pre;
                    if (next >= 0)
                        pre = (tid < JPT) ? g_pA[kc][b][next * JPT + tid]
                                          : g_pB[kc][b][next * JPT + tid - JPT];

                    #pragma unroll 8
                    for (int j = 0; j < JPT; j++) {
                        ulonglong2 A = sAb[buf][j];
                        ulonglong2 B = sBb[buf][j];
                        #pragma unroll
                        for (int p = 0; p < PPT; p++) {
                            unsigned long long e = fma2(qxd[p], A.x, B.y);
                            e = fma2(qyd[p], A.y, e);
                            e = fma2(qzd[p], B.x, e);
                            float2 ef = unpack2(e);
                            emin[p] = fminf(emin[p], fminf(ef.x, ef.y));
                        }
                    }
                    float bd = fmaxf(emin[0] + q2[0], emin[1] + q2[1]);
                    #pragma unroll
                    for (int s2 = 16; s2 > 0; s2 >>= 1)
                        bd = fmaxf(bd, __shfl_xor_sync(0xffffffffu, bd, s2));
                    if (lane == 0) bbw[w] = bd;
                    if (next >= 0) {
                        if (tid < JPT) sAb[buf ^ 1][tid] = pre;
                        else           sBb[buf ^ 1][tid - JPT] = pre;
                    }
                    __syncthreads();
                    bb = fmaxf(fmaxf(bbw[0], bbw[1]), fmaxf(bbw[2], bbw[3]));
                    if (next < 0) break;
                    float sgap = qzmin - spre[next];
                    if (sgap > 0.0f && sgap * sgap >= bb) break;
                    cur = next;
                    buf ^= 1;
                }
            }
        }
    }

    // store this split's partial mins (d = emin + q2)
    #pragma unroll
    for (int p = 0; p < PPT; p++)
        g_pm[dir][b][qb][split][p * TPB + tid] = emin[p] + q2[p];

    // ---- group arrive: last of the NSPLIT co-blocks finishes the group ----
    __threadfence();
    if (tid == 0) {
        int old = atomicAdd(&g_ctr_g[dir][b][qb], 1);
        sh_last = (old == NSPLIT - 1) ? 1 : 0;
        if (sh_last) g_ctr_g[dir][b][qb] = 0;   // reset for graph replay
    }
    __syncthreads();
    if (!sh_last) return;

    {
        float m0 = fminf(g_pm[dir][b][qb][0][tid],
                         g_pm[dir][b][qb][1][tid]);
        float m1 = fminf(g_pm[dir][b][qb][0][tid + TPB],
                         g_pm[dir][b][qb][1][tid + TPB]);
        float sd = m0 + m1;
        float se = __expf(-m0 * INV_C) + __expf(-m1 * INV_C);
        #pragma unroll
        for (int s = 16; s > 0; s >>= 1) {
            sd += __shfl_xor_sync(0xffffffffu, sd, s);
            se += __shfl_xor_sync(0xffffffffu, se, s);
        }
        if (lane == 0) { red[w][0] = sd; red[w][1] = se; }
        __syncthreads();
        if (tid == 0) {
            g_r3[dir][b][qb][0] = red[0][0] + red[1][0] + red[2][0] + red[3][0];
            g_r3[dir][b][qb][1] = red[0][1] + red[1][1] + red[2][1] + red[3][1];
        }
    }

    global_arrive(dsw, out, tid, &sh_final);
}

extern "C" void kernel_launch(void* const* d_in, const int* in_sizes, int n_in,
                              void* d_out, int out_size)
{
    const float* pred_pc   = (const float*)d_in[0];
    const float* target_pc = (const float*)d_in[1];
    const float* dfeat     = (const float*)d_in[2];
    const float* dsw       = (const float*)d_in[3];
    const float* W1 = (const float*)d_in[4];
    const float* b1 = (const float*)d_in[5];
    const float* W2 = (const float*)d_in[6];
    const float* b2 = (const float*)d_in[7];
    const float* W3 = (const float*)d_in[8];
    const float* b3 = (const float*)d_in[9];
    const int*   labels = (const int*)d_in[10];
    float* out = (float*)d_out;

    bucket_kernel<<<16, 512>>>(pred_pc, target_pc);

    // (16, 5, 8): y<4 chamfer (dir = y&1, split = y>>1); y==4,x==0 domain.
    dim3 grid(NQB, 2 * NSPLIT + 1, BATCH);
    chamfer_kernel<<<grid, TPB>>>(dfeat, W1, b1, W2, b2, W3, b3,
                                  labels, dsw, out);
}